// round 16
// baseline (speedup 1.0000x reference)
#include <cuda_runtime.h>
#include <mma.h>
#include <math.h>

using namespace nvcuda;

#define B 8
#define N 256
#define BN 2048
#define NID 64
#define V 128
#define GH 128
#define PHI 256
#define RHO 128
#define EPS 1e-5f

// ---------------- scratch ----------------
__device__ float g_H[BN * GH];
__device__ float g_H2[BN * GH];
__device__ float g_agg[BN * GH];
__device__ float g_Spos[BN * GH];
__device__ float g_Sneg[BN * GH];
__device__ float g_phi[BN * PHI];
__device__ float g_sums[8 * 2 * B * PHI];
__device__ float g_mskT[BN * N];     // sign(A) transposed: [b][j][i]
__device__ float g_amskT[BN * N];    // |sign(A)| transposed: [b][j][i]
__device__ float2 g_rcp[BN];         // (1/max(cntPos,1), 1/max(cntNeg,1)) per target j

// ---------------- K0: prep — transposed masks + counts ----------------
// grid (8, 32), 256 threads. Block handles batch b, j-range [jc, jc+8).
__global__ void k_prep(const float* __restrict__ A) {
    int b = blockIdx.x, jc = blockIdx.y * 8;
    int t = threadIdx.x;              // 256
    __shared__ float tile[32][9];
    int jr = t >> 5;                  // 0..7 (warp id) -> j = jc + jr
    int ii = t & 31;                  // lane -> i within chunk
    int j = jc + jr;
    float cp = 0.f, cn = 0.f;
    for (int i0 = 0; i0 < N; i0 += 32) {
        tile[t >> 3][t & 7] = A[(b * N + i0 + (t >> 3)) * N + jc + (t & 7)];
        __syncthreads();
        float a = tile[ii][jr];
        float p = (a > 0.f) ? 1.f : 0.f;
        float n = (a < 0.f) ? 1.f : 0.f;
        cp += p; cn += n;
        g_mskT[((b << 8) + j) * N + i0 + ii] = p - n;
        g_amskT[((b << 8) + j) * N + i0 + ii] = p + n;
        __syncthreads();
    }
#pragma unroll
    for (int o = 16; o > 0; o >>= 1) {
        cp += __shfl_xor_sync(0xffffffff, cp, o);
        cn += __shfl_xor_sync(0xffffffff, cn, o);
    }
    if (ii == 0)
        g_rcp[(b << 8) + j] = make_float2(1.f / fmaxf(cp, 1.f), 1.f / fmaxf(cn, 1.f));
}

// ---------------- K1: embedding (512 thr, 8 rows) ----------------
__global__ void __launch_bounds__(512) k_emb(const float* __restrict__ X,
                      const float* __restrict__ W1, const float* __restrict__ b1,
                      const float* __restrict__ W2, const float* __restrict__ b2) {
    int r0 = blockIdx.x * 8;
    int t = threadIdx.x;
    int col = t & 127, rg = t >> 7;
    __shared__ __align__(16) float xsT[NID * 12];
    __shared__ __align__(16) float h1T[V * 12];

    if (t < 8 * NID) {
        int rr = t >> 6, kk = t & 63;
        xsT[kk * 12 + rr] = X[(r0 + rr) * NID + kk];
    }
    __syncthreads();
    float a0, a1;
    a0 = a1 = b1[col];
#pragma unroll 8
    for (int k = 0; k < NID; k++) {
        float w = W1[k * V + col];
        float2 x = *(const float2*)&xsT[k * 12 + rg * 2];
        a0 = fmaf(x.x, w, a0); a1 = fmaf(x.y, w, a1);
    }
    *(float2*)&h1T[col * 12 + rg * 2] = make_float2(fmaxf(a0, 0.f), fmaxf(a1, 0.f));
    __syncthreads();
    a0 = a1 = b2[col];
#pragma unroll 8
    for (int k = 0; k < V; k++) {
        float w = W2[k * V + col];
        float2 x = *(const float2*)&h1T[k * 12 + rg * 2];
        a0 = fmaf(x.x, w, a0); a1 = fmaf(x.y, w, a1);
    }
    int base = (r0 + rg * 2) * V + col;
    g_H[base] = a0; g_H[base + V] = a1;
}

// ---------------- K2a: masked-mean reduce via TF32 WMMA ----------------
// grid 64: b = bx>>3, jt = (bx>>1)&3, ct = bx&1. 256 threads (8 warps).
__global__ void __launch_bounds__(256) k_red_tc() {
    int bx = blockIdx.x;
    int b = bx >> 3, jt = (bx >> 1) & 3, ct = bx & 1;
    int j0 = jt * 64, c0 = ct * 64;
    int t = threadIdx.x;
    int w = t >> 5;
    __shared__ __align__(16) float sb[9728];
    float* smT = sb;            // [64][40] signed masks (tf32)
    float* amT = sb + 2560;     // [64][40] abs masks
    float* hHi = sb + 5120;     // [32][72] H hi
    float* hLo = sb + 7424;     // [32][72] H lo

    wmma::fragment<wmma::accumulator, 16, 16, 8, float> accS[2], accA[2];
    wmma::fill_fragment(accS[0], 0.f); wmma::fill_fragment(accS[1], 0.f);
    wmma::fill_fragment(accA[0], 0.f); wmma::fill_fragment(accA[1], 0.f);

    int mi = w & 3;
    int np = w >> 2;            // n-tile pair: {np, np+2}

    for (int kc = 0; kc < 8; kc++) {
        int k0 = kc * 32;
        {
            int row = t >> 2, cs = (t & 3) * 8;
            const float* s1 = &g_mskT[((b << 8) + j0 + row) * N + k0 + cs];
            const float* s2 = &g_amskT[((b << 8) + j0 + row) * N + k0 + cs];
#pragma unroll
            for (int q = 0; q < 8; q++) {
                smT[row * 40 + cs + q] = wmma::__float_to_tf32(s1[q]);
                amT[row * 40 + cs + q] = wmma::__float_to_tf32(s2[q]);
            }
        }
        {
            int row = t >> 3, cs = (t & 7) * 8;
            const float* s = &g_H[((b << 8) + k0 + row) * GH + c0 + cs];
#pragma unroll
            for (int q = 0; q < 8; q++) {
                float x = s[q];
                float hi = wmma::__float_to_tf32(x);
                hHi[row * 72 + cs + q] = hi;
                hLo[row * 72 + cs + q] = wmma::__float_to_tf32(x - hi);
            }
        }
        __syncthreads();
#pragma unroll
        for (int ks = 0; ks < 4; ks++) {
            int k = ks * 8;
            wmma::fragment<wmma::matrix_a, 16, 16, 8, wmma::precision::tf32, wmma::row_major> aS, aA;
            wmma::load_matrix_sync(aS, &smT[mi * 16 * 40 + k], 40);
            wmma::load_matrix_sync(aA, &amT[mi * 16 * 40 + k], 40);
#pragma unroll
            for (int p = 0; p < 2; p++) {
                int nt = np + p * 2;
                wmma::fragment<wmma::matrix_b, 16, 16, 8, wmma::precision::tf32, wmma::row_major> bH, bL;
                wmma::load_matrix_sync(bH, &hHi[k * 72 + nt * 16], 72);
                wmma::load_matrix_sync(bL, &hLo[k * 72 + nt * 16], 72);
                wmma::mma_sync(accS[p], aS, bH, accS[p]);
                wmma::mma_sync(accS[p], aS, bL, accS[p]);
                wmma::mma_sync(accA[p], aA, bH, accA[p]);
                wmma::mma_sync(accA[p], aA, bL, accA[p]);
            }
        }
        __syncthreads();
    }
    float* sbS = sb;            // [64][64]
    float* sbA = sb + 4096;     // [64][64]
#pragma unroll
    for (int p = 0; p < 2; p++) {
        int nt = np + p * 2;
        wmma::store_matrix_sync(&sbS[mi * 16 * 64 + nt * 16], accS[p], 64, wmma::mem_row_major);
        wmma::store_matrix_sync(&sbA[mi * 16 * 64 + nt * 16], accA[p], 64, wmma::mem_row_major);
    }
    __syncthreads();
    {
        int cc = t & 63, rbase = (t >> 6) * 16;
#pragma unroll
        for (int r = 0; r < 16; r++) {
            int jj = rbase + r;
            float S = sbS[jj * 64 + cc];
            float Aa = sbA[jj * 64 + cc];
            float2 rcp = g_rcp[(b << 8) + j0 + jj];
            int orow = ((b << 8) + j0 + jj) * GH + c0 + cc;
            g_Spos[orow] = (Aa + S) * 0.5f * rcp.x;
            g_Sneg[orow] = (Aa - S) * 0.5f * rcp.y;
        }
    }
}

// ---------------- K2b: RGCN 3-way matmul (512 thr, 8 rows) ----------------
__global__ void __launch_bounds__(512) k_rgcnmm(const float* __restrict__ Wrel,
                                                const float* __restrict__ Wroot,
                                                const float* __restrict__ bias) {
    int r0 = blockIdx.x * 8;
    int t = threadIdx.x;
    int col = t & 127, iseg = t >> 7;
    __shared__ __align__(16) float hrT[GH * 12];
    __shared__ __align__(16) float snT[GH * 12];
    __shared__ __align__(16) float spT[GH * 12];

    for (int idx = t; idx < 8 * GH; idx += 512) {
        int rr = idx >> 7, kk = idx & 127;
        int g = (r0 + rr) * GH + kk;
        hrT[kk * 12 + rr] = g_H[g];
        snT[kk * 12 + rr] = g_Sneg[g];
        spT[kk * 12 + rr] = g_Spos[g];
    }
    __syncthreads();

    const float* W0 = Wrel;
    const float* W1 = Wrel + V * GH;
    float a0, a1;
    a0 = a1 = bias[col];
#pragma unroll 8
    for (int k = 0; k < GH; k++) {
        float wr = Wroot[k * GH + col];
        float w0 = W0[k * GH + col];
        float w1 = W1[k * GH + col];
        float2 h = *(const float2*)&hrT[k * 12 + iseg * 2];
        float2 sn = *(const float2*)&snT[k * 12 + iseg * 2];
        float2 sp = *(const float2*)&spT[k * 12 + iseg * 2];
        a0 = fmaf(h.x, wr, a0);  a1 = fmaf(h.y, wr, a1);
        a0 = fmaf(sn.x, w0, a0); a1 = fmaf(sn.y, w0, a1);
        a0 = fmaf(sp.x, w1, a0); a1 = fmaf(sp.y, w1, a1);
    }
    int base = (r0 + iseg * 2) * GH + col;
    g_H2[base] = a0; g_H2[base + GH] = a1;
}

// ---------------- K3a: scatter via TF32 WMMA: agg = |A| @ H2 ----------------
__global__ void __launch_bounds__(256) k_scat_tc(const float* __restrict__ A) {
    int bx = blockIdx.x;
    int b = bx >> 3, it = (bx >> 1) & 3, ct = bx & 1;
    int i0 = it * 64, c0 = ct * 64;
    int t = threadIdx.x;
    int w = t >> 5;
    __shared__ __align__(16) float sb[9728];
    float* aHi = sb;            // [64][40]
    float* aLo = sb + 2560;
    float* hHi = sb + 5120;     // [32][72]
    float* hLo = sb + 7424;

    wmma::fragment<wmma::accumulator, 16, 16, 8, float> acc[2];
    wmma::fill_fragment(acc[0], 0.f); wmma::fill_fragment(acc[1], 0.f);
    int mi = w & 3;
    int np = w >> 2;

    for (int kc = 0; kc < 8; kc++) {
        int k0 = kc * 32;
        {
            int row = t >> 2, cs = (t & 3) * 8;
            const float* s = &A[(b * N + i0 + row) * N + k0 + cs];
#pragma unroll
            for (int q = 0; q < 8; q++) {
                float x = fabsf(s[q]);
                float hi = wmma::__float_to_tf32(x);
                aHi[row * 40 + cs + q] = hi;
                aLo[row * 40 + cs + q] = wmma::__float_to_tf32(x - hi);
            }
        }
        {
            int row = t >> 3, cs = (t & 7) * 8;
            const float* s = &g_H2[((b << 8) + k0 + row) * GH + c0 + cs];
#pragma unroll
            for (int q = 0; q < 8; q++) {
                float x = s[q];
                float hi = wmma::__float_to_tf32(x);
                hHi[row * 72 + cs + q] = hi;
                hLo[row * 72 + cs + q] = wmma::__float_to_tf32(x - hi);
            }
        }
        __syncthreads();
#pragma unroll
        for (int ks = 0; ks < 4; ks++) {
            int k = ks * 8;
            wmma::fragment<wmma::matrix_a, 16, 16, 8, wmma::precision::tf32, wmma::row_major> aH, aL;
            wmma::load_matrix_sync(aH, &aHi[mi * 16 * 40 + k], 40);
            wmma::load_matrix_sync(aL, &aLo[mi * 16 * 40 + k], 40);
#pragma unroll
            for (int p = 0; p < 2; p++) {
                int nt = np + p * 2;
                wmma::fragment<wmma::matrix_b, 16, 16, 8, wmma::precision::tf32, wmma::row_major> bH, bL;
                wmma::load_matrix_sync(bH, &hHi[k * 72 + nt * 16], 72);
                wmma::load_matrix_sync(bL, &hLo[k * 72 + nt * 16], 72);
                wmma::mma_sync(acc[p], aH, bH, acc[p]);
                wmma::mma_sync(acc[p], aH, bL, acc[p]);
                wmma::mma_sync(acc[p], aL, bH, acc[p]);
            }
        }
        __syncthreads();
    }
    float* sbO = sb;            // [64][64]
#pragma unroll
    for (int p = 0; p < 2; p++) {
        int nt = np + p * 2;
        wmma::store_matrix_sync(&sbO[mi * 16 * 64 + nt * 16], acc[p], 64, wmma::mem_row_major);
    }
    __syncthreads();
    {
        int cc = t & 63, rbase = (t >> 6) * 16;
#pragma unroll
        for (int r = 0; r < 16; r++) {
            int jj = rbase + r;
            g_agg[((b << 8) + i0 + jj) * GH + c0 + cc] = sbO[jj * 64 + cc];
        }
    }
}

// ---------------- K3b: layernorm + relu + 2-layer MLP + H += ----------------
__global__ void __launch_bounds__(512) k_normmlp(const float* __restrict__ norm_g, const float* __restrict__ norm_b,
                                                 const float* __restrict__ law, const float* __restrict__ lab,
                                                 const float* __restrict__ lbw, const float* __restrict__ lbb) {
    int r0 = blockIdx.x * 8;
    int t = threadIdx.x;
    int col = t & 127, jseg = t >> 7;
    int wp = t >> 5, lane = t & 31;
    __shared__ float buf[8 * 128];
    __shared__ __align__(16) float bufT[GH * 12];
    __shared__ float stat[8][2];

    for (int idx = t; idx < 8 * GH; idx += 512)
        buf[idx] = g_agg[r0 * GH + idx];
    __syncthreads();

    if (wp < 8) {
        float s = 0.f, sq = 0.f;
#pragma unroll
        for (int c = 0; c < 4; c++) {
            float v = buf[wp * 128 + lane + c * 32];
            s += v; sq = fmaf(v, v, sq);
        }
#pragma unroll
        for (int o = 16; o > 0; o >>= 1) {
            s += __shfl_xor_sync(0xffffffff, s, o);
            sq += __shfl_xor_sync(0xffffffff, sq, o);
        }
        if (lane == 0) {
            float mean = s * (1.f / GH);
            float var = sq * (1.f / GH) - mean * mean;
            stat[wp][0] = mean;
            stat[wp][1] = rsqrtf(var + EPS);
        }
    }
    __syncthreads();
    for (int idx = t; idx < 8 * GH; idx += 512) {
        int r = idx & 7, cc = idx >> 3;
        float v = (buf[r * 128 + cc] - stat[r][0]) * stat[r][1] * norm_g[cc] + norm_b[cc];
        bufT[cc * 12 + r] = fmaxf(v, 0.f);
    }
    __syncthreads();

    float a0, a1;
    a0 = a1 = lab[col];
#pragma unroll 8
    for (int k = 0; k < GH; k++) {
        float w = law[k * GH + col];
        float2 x = *(const float2*)&bufT[k * 12 + jseg * 2];
        a0 = fmaf(x.x, w, a0); a1 = fmaf(x.y, w, a1);
    }
    __syncthreads();
    *(float2*)&bufT[col * 12 + jseg * 2] = make_float2(fmaxf(a0, 0.f), fmaxf(a1, 0.f));
    __syncthreads();

    a0 = a1 = lbb[col];
#pragma unroll 8
    for (int k = 0; k < GH; k++) {
        float w = lbw[k * GH + col];
        float2 x = *(const float2*)&bufT[k * 12 + jseg * 2];
        a0 = fmaf(x.x, w, a0); a1 = fmaf(x.y, w, a1);
    }
    int base = (r0 + jseg * 2) * GH + col;
    g_H[base] += a0; g_H[base + GH] += a1;
}

// ---------------- K4: phi MLP (512 threads, 8 rows, 4 rows/thread) ----------------
__global__ void __launch_bounds__(512) k_phi(const float* __restrict__ w1, const float* __restrict__ b1,
                                             const float* __restrict__ w2, const float* __restrict__ b2) {
    int r0 = blockIdx.x * 8;
    int t = threadIdx.x;
    int col = t & 255, rg = t >> 8;
    __shared__ __align__(16) float hT[GH * 12];
    __shared__ __align__(16) float h1T[PHI * 12];

    for (int idx = t; idx < 8 * GH; idx += 512) {
        int rr = idx >> 7, kk = idx & 127;
        hT[kk * 12 + rr] = g_H[(r0 + rr) * GH + kk];
    }
    __syncthreads();
    float a0, a1, a2, a3;
    a0 = a1 = a2 = a3 = b1[col];
#pragma unroll 8
    for (int k = 0; k < GH; k++) {
        float w = w1[k * PHI + col];
        float4 x = *(const float4*)&hT[k * 12 + rg * 4];
        a0 = fmaf(x.x, w, a0); a1 = fmaf(x.y, w, a1);
        a2 = fmaf(x.z, w, a2); a3 = fmaf(x.w, w, a3);
    }
    *(float4*)&h1T[col * 12 + rg * 4] =
        make_float4(fmaxf(a0, 0.f), fmaxf(a1, 0.f), fmaxf(a2, 0.f), fmaxf(a3, 0.f));
    __syncthreads();
    a0 = a1 = a2 = a3 = b2[col];
#pragma unroll 8
    for (int k = 0; k < PHI; k++) {
        float w = w2[k * PHI + col];
        float4 x = *(const float4*)&h1T[k * 12 + rg * 4];
        a0 = fmaf(x.x, w, a0); a1 = fmaf(x.y, w, a1);
        a2 = fmaf(x.z, w, a2); a3 = fmaf(x.w, w, a3);
    }
    int base = (r0 + rg * 4) * PHI + col;
    g_phi[base] = fmaxf(a0, 0.f);
    g_phi[base + PHI] = fmaxf(a1, 0.f);
    g_phi[base + 2 * PHI] = fmaxf(a2, 0.f);
    g_phi[base + 3 * PHI] = fmaxf(a3, 0.f);
}

// ---------------- K5: masked pooling ----------------
__global__ void k_pool(const float* __restrict__ home_mask) {
    int b = blockIdx.x;
    int seg = blockIdx.y;
    int p = threadIdx.x;          // 256
    const float* pb = g_phi + b * N * PHI;
    const float* hm = home_mask + b * N;
    float hs = 0.f, as = 0.f;
    int n0 = seg * 32;
#pragma unroll 8
    for (int n = n0; n < n0 + 32; n++) {
        float v = pb[n * PHI + p];
        float m = hm[n];
        hs = fmaf(v, m, hs);
        as = fmaf(v, 1.f - m, as);
    }
    g_sums[((seg * 2 + 0) * B + b) * PHI + p] = hs;
    g_sums[((seg * 2 + 1) * B + b) * PHI + p] = as;
}

// ---------------- K6: rho head ----------------
__global__ void k_rho(const float* __restrict__ w1, const float* __restrict__ b1,
                      const float* __restrict__ w2, float* __restrict__ out) {
    int b = blockIdx.x;
    int t = threadIdx.x;          // 128
    __shared__ float hs[PHI];
    __shared__ float as[PHI];
    __shared__ float red[RHO];
    for (int c = t; c < PHI; c += 128) {
        float h = 0.f, a = 0.f;
#pragma unroll
        for (int seg = 0; seg < 8; seg++) {
            h += g_sums[((seg * 2 + 0) * B + b) * PHI + c];
            a += g_sums[((seg * 2 + 1) * B + b) * PHI + c];
        }
        hs[c] = h; as[c] = a;
    }
    __syncthreads();
    float rh = b1[t], ra = b1[t];
#pragma unroll 8
    for (int k = 0; k < PHI; k++) {
        float w = w1[k * RHO + t];
        rh = fmaf(hs[k], w, rh);
        ra = fmaf(as[k], w, ra);
    }
    rh = fmaxf(rh, 0.f);
    ra = fmaxf(ra, 0.f);
    red[t] = (rh - ra) * w2[t];
    __syncthreads();
    for (int s = RHO / 2; s > 0; s >>= 1) {
        if (t < s) red[t] += red[t + s];
        __syncthreads();
    }
    if (t == 0) out[b] = 0.5f + 0.5f * tanhf(red[0]);
}

// ---------------- launch ----------------
extern "C" void kernel_launch(void* const* d_in, const int* in_sizes, int n_in,
                              void* d_out, int out_size) {
    const float* A        = (const float*)d_in[0];
    const float* X        = (const float*)d_in[1];
    const float* home     = (const float*)d_in[2];
    const float* emb1_w   = (const float*)d_in[3];
    const float* emb1_b   = (const float*)d_in[4];
    const float* emb2_w   = (const float*)d_in[5];
    const float* emb2_b   = (const float*)d_in[6];
    const float* rgcn_w0  = (const float*)d_in[7];
    const float* root0    = (const float*)d_in[8];
    const float* bias0    = (const float*)d_in[9];
    const float* law0     = (const float*)d_in[10];
    const float* lab0     = (const float*)d_in[11];
    const float* lbw0     = (const float*)d_in[12];
    const float* lbb0     = (const float*)d_in[13];
    const float* rgcn_w1  = (const float*)d_in[14];
    const float* root1    = (const float*)d_in[15];
    const float* bias1    = (const float*)d_in[16];
    const float* law1     = (const float*)d_in[17];
    const float* lab1     = (const float*)d_in[18];
    const float* lbw1     = (const float*)d_in[19];
    const float* lbb1     = (const float*)d_in[20];
    const float* norm_g   = (const float*)d_in[21];
    const float* norm_b   = (const float*)d_in[22];
    const float* phi_w1   = (const float*)d_in[23];
    const float* phi_b1   = (const float*)d_in[24];
    const float* phi_w2   = (const float*)d_in[25];
    const float* phi_b2   = (const float*)d_in[26];
    const float* rho_w1   = (const float*)d_in[27];
    const float* rho_b1   = (const float*)d_in[28];
    const float* rho_w2   = (const float*)d_in[29];
    float* out = (float*)d_out;

    dim3 pgrid(8, 32);
    k_prep<<<pgrid, 256>>>(A);
    k_emb<<<256, 512>>>(X, emb1_w, emb1_b, emb2_w, emb2_b);

    k_red_tc<<<64, 256>>>();
    k_rgcnmm<<<256, 512>>>(rgcn_w0, root0, bias0);
    k_scat_tc<<<64, 256>>>(A);
    k_normmlp<<<256, 512>>>(norm_g, norm_b, law0, lab0, lbw0, lbb0);

    k_red_tc<<<64, 256>>>();
    k_rgcnmm<<<256, 512>>>(rgcn_w1, root1, bias1);
    k_scat_tc<<<64, 256>>>(A);
    k_normmlp<<<256, 512>>>(norm_g, norm_b, law1, lab1, lbw1, lbb1);

    k_phi<<<256, 512>>>(phi_w1, phi_b1, phi_w2, phi_b2);
    dim3 pg(B, 8);
    k_pool<<<pg, 256>>>(home);
    k_rho<<<B, 128>>>(rho_w1, rho_b1, rho_w2, out);
}

// round 17
// speedup vs baseline: 1.1564x; 1.1564x over previous
#include <cuda_runtime.h>
#include <math.h>

#define B 8
#define N 256
#define BN 2048
#define NID 64
#define V 128
#define GH 128
#define PHI 256
#define RHO 128
#define EPS 1e-5f

// ---------------- scratch ----------------
__device__ float g_H[BN * GH];
__device__ float g_H2[BN * GH];
__device__ float g_phi[BN * PHI];
__device__ float g_sums[8 * 2 * B * PHI];
__device__ float g_msk[BN * N];      // sign(A) in {-1,0,1}, layout [b][i][j]
__device__ float2 g_rcp[BN];         // (1/max(cntPos,1), 1/max(cntNeg,1)) per target j

// ---------------- K0: prep  masks + counts ----------------
__global__ void k_prep(const float* __restrict__ A) {
    int b = blockIdx.x, jc = blockIdx.y * 32;
    int t = threadIdx.x;              // 256
    int j = jc + (t & 31), iseg = t >> 5;   // 8 segs of 32 i
    const float* Ab = A + b * N * N;
    float cp = 0.f, cn = 0.f;
#pragma unroll 4
    for (int ii = 0; ii < 32; ii++) {
        int i = iseg * 32 + ii;
        float a = Ab[i * N + j];
        float p = (a > 0.f) ? 1.f : 0.f;
        float n = (a < 0.f) ? 1.f : 0.f;
        cp += p; cn += n;
        g_msk[((b << 8) + i) * N + j] = p - n;
    }
    __shared__ float sp[8][32], sn[8][32];
    sp[iseg][t & 31] = cp; sn[iseg][t & 31] = cn;
    __syncthreads();
    if (t < 32) {
        float tp = 0.f, tn = 0.f;
#pragma unroll
        for (int s = 0; s < 8; s++) { tp += sp[s][t]; tn += sn[s][t]; }
        g_rcp[(b << 8) + jc + t] = make_float2(1.f / fmaxf(tp, 1.f), 1.f / fmaxf(tn, 1.f));
    }
}

// ---------------- K1: embedding (512 thr, 8 rows, 2 rows/thread) ----------------
__global__ void __launch_bounds__(512) k_emb(const float* __restrict__ X,
                      const float* __restrict__ W1, const float* __restrict__ b1,
                      const float* __restrict__ W2, const float* __restrict__ b2) {
    int r0 = blockIdx.x * 8;
    int t = threadIdx.x;
    int col = t & 127, rg = t >> 7;
    __shared__ __align__(16) float xsT[NID * 12];
    __shared__ __align__(16) float h1T[V * 12];

    if (t < 8 * NID) {
        int rr = t >> 6, kk = t & 63;
        xsT[kk * 12 + rr] = X[(r0 + rr) * NID + kk];
    }
    __syncthreads();
    float a0, a1;
    a0 = a1 = b1[col];
#pragma unroll 8
    for (int k = 0; k < NID; k++) {
        float w = W1[k * V + col];
        float2 x = *(const float2*)&xsT[k * 12 + rg * 2];
        a0 = fmaf(x.x, w, a0); a1 = fmaf(x.y, w, a1);
    }
    *(float2*)&h1T[col * 12 + rg * 2] = make_float2(fmaxf(a0, 0.f), fmaxf(a1, 0.f));
    __syncthreads();
    a0 = a1 = b2[col];
#pragma unroll 8
    for (int k = 0; k < V; k++) {
        float w = W2[k * V + col];
        float2 x = *(const float2*)&h1T[k * 12 + rg * 2];
        a0 = fmaf(x.x, w, a0); a1 = fmaf(x.y, w, a1);
    }
    int base = (r0 + rg * 2) * V + col;
    g_H[base] = a0; g_H[base + V] = a1;
}

// ---------------- K2: fused RGCN, tile-4 (512 blocks x 512 threads) ----------------
// block = (b, j-tile of 4); 512 threads = 4 i-segments x 128 cols
__global__ void __launch_bounds__(512) k_rgcn(const float* __restrict__ Wrel,
                                              const float* __restrict__ Wroot,
                                              const float* __restrict__ bias) {
    int b = blockIdx.x >> 6;
    int j0 = (blockIdx.x & 63) * 4;
    int t = threadIdx.x;
    int col = t & 127, iseg = t >> 7;     // 0..3
    __shared__ __align__(16) float msk_s[N * 4];    // 4KB  [i][4]
    __shared__ float sAccS[4 * 128], sAccA[4 * 128];// 4KB
    __shared__ float hrB[4 * 128];                  // 2KB  [row][k]
    __shared__ float2 rcp_s[4];

    // stage masks: 256 threads do float4 each (j0 16B-aligned)
    if (t < N) {
        *(float4*)&msk_s[t * 4] = *(const float4*)&g_msk[((b << 8) + t) * N + j0];
    }
    if (t < 4) rcp_s[t] = g_rcp[(b << 8) + j0 + t];
    __syncthreads();

    float accS[4], accA[4];
#pragma unroll
    for (int jj = 0; jj < 4; jj++) { accS[jj] = 0.f; accA[jj] = 0.f; }
    const float* Hb = g_H + ((b << 8) + (iseg << 6)) * V + col;
#pragma unroll 8
    for (int ii = 0; ii < 64; ii++) {
        float h = Hb[ii * V];
        float4 m = *(const float4*)&msk_s[((iseg << 6) + ii) * 4];
        accS[0] = fmaf(m.x, h, accS[0]); accA[0] = fmaf(fabsf(m.x), h, accA[0]);
        accS[1] = fmaf(m.y, h, accS[1]); accA[1] = fmaf(fabsf(m.y), h, accA[1]);
        accS[2] = fmaf(m.z, h, accS[2]); accA[2] = fmaf(fabsf(m.z), h, accA[2]);
        accS[3] = fmaf(m.w, h, accS[3]); accA[3] = fmaf(fabsf(m.w), h, accA[3]);
    }
    // 4-pass combine
#pragma unroll
    for (int s = 0; s < 4; s++) {
        if (iseg == s) {
            if (s == 0) {
#pragma unroll
                for (int jj = 0; jj < 4; jj++) { sAccS[jj * 128 + col] = accS[jj]; sAccA[jj * 128 + col] = accA[jj]; }
            } else {
#pragma unroll
                for (int jj = 0; jj < 4; jj++) { sAccS[jj * 128 + col] += accS[jj]; sAccA[jj * 128 + col] += accA[jj]; }
            }
        }
        __syncthreads();
    }
    // stage H rows [4][128] coalesced
    {
        int row = t >> 7, k = t & 127;
        hrB[row * 128 + k] = g_H[((b << 8) + j0 + row) * GH + k];
    }
    __syncthreads();

    // matmul: thread (col, iseg=row)
    const float* W0 = Wrel;
    const float* W1 = Wrel + V * GH;
    float rcpP = rcp_s[iseg].x * 0.5f;
    float rcpN = rcp_s[iseg].y * 0.5f;
    float acc = bias[col];
#pragma unroll 4
    for (int k = 0; k < GH; k++) {
        float wr = Wroot[k * GH + col];
        float w0 = W0[k * GH + col];
        float w1 = W1[k * GH + col];
        float sS = sAccS[iseg * 128 + k];
        float sA = sAccA[iseg * 128 + k];
        float hr = hrB[iseg * 128 + k];
        float sp = (sA + sS) * rcpP;
        float sn = (sA - sS) * rcpN;
        acc = fmaf(hr, wr, acc);
        acc = fmaf(sn, w0, acc);
        acc = fmaf(sp, w1, acc);
    }
    g_H2[((b << 8) + j0 + iseg) * GH + col] = acc;
}

// ---------------- K3: fused scatter + layernorm + MLP + H+=, tile-4 ----------------
// block = (b, i-tile of 4); 512 threads = 4 j-segments x 128 cols
__global__ void __launch_bounds__(512) k_scat(const float* __restrict__ A,
                                              const float* __restrict__ norm_g, const float* __restrict__ norm_b,
                                              const float* __restrict__ law, const float* __restrict__ lab,
                                              const float* __restrict__ lbw, const float* __restrict__ lbb) {
    int b = blockIdx.x >> 6;
    int i0 = (blockIdx.x & 63) * 4;
    int t = threadIdx.x;
    int col = t & 127, jseg = t >> 7;     // 0..3
    int wp = t >> 5, lane = t & 31;
    __shared__ __align__(16) float aabT[N * 4];     // 4KB [j][4]
    __shared__ float bufv[4 * 128];                 // 2KB
    __shared__ float buf2[4 * 128];                 // 2KB
    __shared__ float stat[4][2];

    // stage |A| transposed: aabT[j*4+q] = |A[b][i0+q][j]|  (coalesced reads)
    for (int idx = t; idx < 1024; idx += 512) {
        int q = idx >> 8, j = idx & 255;
        aabT[j * 4 + q] = fabsf(A[(b * N + i0 + q) * N + j]);
    }
    __syncthreads();

    float acc4[4];
#pragma unroll
    for (int q = 0; q < 4; q++) acc4[q] = 0.f;
    const float* H2b = g_H2 + ((b << 8) + (jseg << 6)) * GH + col;
#pragma unroll 8
    for (int jj = 0; jj < 64; jj++) {
        float h2 = H2b[jj * GH];
        float4 m = *(const float4*)&aabT[((jseg << 6) + jj) * 4];
        acc4[0] = fmaf(m.x, h2, acc4[0]);
        acc4[1] = fmaf(m.y, h2, acc4[1]);
        acc4[2] = fmaf(m.z, h2, acc4[2]);
        acc4[3] = fmaf(m.w, h2, acc4[3]);
    }
#pragma unroll
    for (int s = 0; s < 4; s++) {
        if (jseg == s) {
            if (s == 0) {
#pragma unroll
                for (int q = 0; q < 4; q++) bufv[q * 128 + col] = acc4[q];
            } else {
#pragma unroll
                for (int q = 0; q < 4; q++) bufv[q * 128 + col] += acc4[q];
            }
        }
        __syncthreads();
    }

    // layernorm stats: warps 0..3 -> row wp
    if (wp < 4) {
        float s = 0.f, sq = 0.f;
#pragma unroll
        for (int c = 0; c < 4; c++) {
            float v = bufv[wp * 128 + lane + c * 32];
            s += v; sq = fmaf(v, v, sq);
        }
#pragma unroll
        for (int o = 16; o > 0; o >>= 1) {
            s += __shfl_xor_sync(0xffffffff, s, o);
            sq += __shfl_xor_sync(0xffffffff, sq, o);
        }
        if (lane == 0) {
            float mean = s * (1.f / GH);
            float var = sq * (1.f / GH) - mean * mean;
            stat[wp][0] = mean;
            stat[wp][1] = rsqrtf(var + EPS);
        }
    }
    __syncthreads();
    // normalize + relu in place (each thread owns one element)
    {
        int row = t >> 7, k = t & 127;
        float v = (bufv[row * 128 + k] - stat[row][0]) * stat[row][1] * norm_g[k] + norm_b[k];
        bufv[row * 128 + k] = fmaxf(v, 0.f);
    }
    __syncthreads();

    // MLP layer 1: thread (col, row=jseg)
    float acc = lab[col];
#pragma unroll 4
    for (int k = 0; k < GH; k++) {
        float w = law[k * GH + col];
        acc = fmaf(bufv[jseg * 128 + k], w, acc);
    }
    buf2[jseg * 128 + col] = fmaxf(acc, 0.f);
    __syncthreads();

    // MLP layer 2 + H +=
    acc = lbb[col];
#pragma unroll 4
    for (int k = 0; k < GH; k++) {
        float w = lbw[k * GH + col];
        acc = fmaf(buf2[jseg * 128 + k], w, acc);
    }
    g_H[((b << 8) + i0 + jseg) * GH + col] += acc;
}

// ---------------- K4: phi MLP (512 threads, 8 rows, 4 rows/thread) ----------------
__global__ void __launch_bounds__(512) k_phi(const float* __restrict__ w1, const float* __restrict__ b1,
                                             const float* __restrict__ w2, const float* __restrict__ b2) {
    int r0 = blockIdx.x * 8;
    int t = threadIdx.x;
    int col = t & 255, rg = t >> 8;
    __shared__ __align__(16) float hT[GH * 12];
    __shared__ __align__(16) float h1T[PHI * 12];

    for (int idx = t; idx < 8 * GH; idx += 512) {
        int rr = idx >> 7, kk = idx & 127;
        hT[kk * 12 + rr] = g_H[(r0 + rr) * GH + kk];
    }
    __syncthreads();
    float a0, a1, a2, a3;
    a0 = a1 = a2 = a3 = b1[col];
#pragma unroll 8
    for (int k = 0; k < GH; k++) {
        float w = w1[k * PHI + col];
        float4 x = *(const float4*)&hT[k * 12 + rg * 4];
        a0 = fmaf(x.x, w, a0); a1 = fmaf(x.y, w, a1);
        a2 = fmaf(x.z, w, a2); a3 = fmaf(x.w, w, a3);
    }
    *(float4*)&h1T[col * 12 + rg * 4] =
        make_float4(fmaxf(a0, 0.f), fmaxf(a1, 0.f), fmaxf(a2, 0.f), fmaxf(a3, 0.f));
    __syncthreads();
    a0 = a1 = a2 = a3 = b2[col];
#pragma unroll 8
    for (int k = 0; k < PHI; k++) {
        float w = w2[k * PHI + col];
        float4 x = *(const float4*)&h1T[k * 12 + rg * 4];
        a0 = fmaf(x.x, w, a0); a1 = fmaf(x.y, w, a1);
        a2 = fmaf(x.z, w, a2); a3 = fmaf(x.w, w, a3);
    }
    int base = (r0 + rg * 4) * PHI + col;
    g_phi[base] = fmaxf(a0, 0.f);
    g_phi[base + PHI] = fmaxf(a1, 0.f);
    g_phi[base + 2 * PHI] = fmaxf(a2, 0.f);
    g_phi[base + 3 * PHI] = fmaxf(a3, 0.f);
}

// ---------------- K5: masked pooling (8 segments of 32 nodes) ----------------
__global__ void k_pool(const float* __restrict__ home_mask) {
    int b = blockIdx.x;
    int seg = blockIdx.y;
    int p = threadIdx.x;          // 256
    const float* pb = g_phi + b * N * PHI;
    const float* hm = home_mask + b * N;
    float hs = 0.f, as = 0.f;
    int n0 = seg * 32;
#pragma unroll 8
    for (int n = n0; n < n0 + 32; n++) {
        float v = pb[n * PHI + p];
        float m = hm[n];
        hs = fmaf(v, m, hs);
        as = fmaf(v, 1.f - m, as);
    }
    g_sums[((seg * 2 + 0) * B + b) * PHI + p] = hs;
    g_sums[((seg * 2 + 1) * B + b) * PHI + p] = as;
}

// ---------------- K6: rho head ----------------
__global__ void k_rho(const float* __restrict__ w1, const float* __restrict__ b1,
                      const float* __restrict__ w2, float* __restrict__ out) {
    int b = blockIdx.x;           // 8
    int t = threadIdx.x;          // 128
    __shared__ float hs[PHI];
    __shared__ float as[PHI];
    __shared__ float red[RHO];
    for (int c = t; c < PHI; c += 128) {
        float h = 0.f, a = 0.f;
#pragma unroll
        for (int seg = 0; seg < 8; seg++) {
            h += g_sums[((seg * 2 + 0) * B + b) * PHI + c];
            a += g_sums[((seg * 2 + 1) * B + b) * PHI + c];
        }
        hs[c] = h; as[c] = a;
    }
    __syncthreads();
    float rh = b1[t], ra = b1[t];
#pragma unroll 8
    for (int k = 0; k < PHI; k++) {
        float w = w1[k * RHO + t];
        rh = fmaf(hs[k], w, rh);
        ra = fmaf(as[k], w, ra);
    }
    rh = fmaxf(rh, 0.f);
    ra = fmaxf(ra, 0.f);
    red[t] = (rh - ra) * w2[t];
    __syncthreads();
    for (int s = RHO / 2; s > 0; s >>= 1) {
        if (t < s) red[t] += red[t + s];
        __syncthreads();
    }
    if (t == 0) out[b] = 0.5f + 0.5f * tanhf(red[0]);
}

// ---------------- launch ----------------
extern "C" void kernel_launch(void* const* d_in, const int* in_sizes, int n_in,
                              void* d_out, int out_size) {
    const float* A        = (const float*)d_in[0];
    const float* X        = (const float*)d_in[1];
    const float* home     = (const float*)d_in[2];
    const float* emb1_w   = (const float*)d_in[3];
    const float* emb1_b   = (const float*)d_in[4];
    const float* emb2_w   = (const float*)d_in[5];
    const float* emb2_b   = (const float*)d_in[6];
    const float* rgcn_w0  = (const float*)d_in[7];
    const float* root0    = (const float*)d_in[8];
    const float* bias0    = (const float*)d_in[9];
    const float* law0     = (const float*)d_in[10];
    const float* lab0     = (const float*)d_in[11];
    const float* lbw0     = (const float*)d_in[12];
    const float* lbb0     = (const float*)d_in[13];
    const float* rgcn_w1  = (const float*)d_in[14];
    const float* root1    = (const float*)d_in[15];
    const float* bias1    = (const float*)d_in[16];
    const float* law1     = (const float*)d_in[17];
    const float* lab1     = (const float*)d_in[18];
    const float* lbw1     = (const float*)d_in[19];
    const float* lbb1     = (const float*)d_in[20];
    const float* norm_g   = (const float*)d_in[21];
    const float* norm_b   = (const float*)d_in[22];
    const float* phi_w1   = (const float*)d_in[23];
    const float* phi_b1   = (const float*)d_in[24];
    const float* phi_w2   = (const float*)d_in[25];
    const float* phi_b2   = (const float*)d_in[26];
    const float* rho_w1   = (const float*)d_in[27];
    const float* rho_b1   = (const float*)d_in[28];
    const float* rho_w2   = (const float*)d_in[29];
    float* out = (float*)d_out;

    dim3 pgrid(8, 8);
    k_prep<<<pgrid, 256>>>(A);
    k_emb<<<256, 512>>>(X, emb1_w, emb1_b, emb2_w, emb2_b);

    k_rgcn<<<512, 512>>>(rgcn_w0, root0, bias0);
    k_scat<<<512, 512>>>(A, norm_g, norm_b, law0, lab0, lbw0, lbb0);

    k_rgcn<<<512, 512>>>(rgcn_w1, root1, bias1);
    k_scat<<<512, 512>>>(A, norm_g, norm_b, law1, lab1, lbw1, lbb1);

    k_phi<<<256, 512>>>(phi_w1, phi_b1, phi_w2, phi_b2);
    dim3 pg(B, 8);
    k_pool<<<pg, 256>>>(home);
    k_rho<<<B, 128>>>(rho_w1, rho_b1, rho_w2, out);
}